// round 13
// baseline (speedup 1.0000x reference)
#include <cuda_runtime.h>
#include <cstdint>
#include <math.h>

// ---------------------------------------------------------------------------
// Fused dequant -> multiply -> requant (layout proven by R6-R12 passes):
//   inputs a,b : int32 buffers holding promoted int8 values (67,108,864 elems)
//   scales     : float32[D=1024] each (scale_a, scale_b, scale_out)
//   output     : float32[n + D]; [0,n) = quantized values, [n,n+D) = scale_out
//   out[i] = (float) clip(round_half_even((a*sa)*(b*sb)/so), -128, 127)
//
// R13 (final form). Measured evidence R10-R12: DRAM pinned ~81% (6.45TB/s)
// for both the 256-bit register path (kernel 118.6us) and the cp.async
// pipeline (120.1/120.4us) -> 2R:1W DRAM turnaround wall; cp.async retired.
// This round: v8 register path as primary + pointer-increment strides
// (removes per-iteration 64-bit address IMADs). Everything else frozen:
// one-wave 1184x256 grid, __launch_bounds__(256,8), .cs streaming hints,
// fused scale_out tail echo, fp32 __fdiv_rn combined scales.
// ---------------------------------------------------------------------------

__device__ __forceinline__ float requant1(float prod, float c) {
    float q = rintf(prod * c);                    // round half to even
    return fminf(fmaxf(q, -128.0f), 127.0f);
}

// vec = 8 elements: one 256-bit load per tensor + one 256-bit store per iter
__global__ void __launch_bounds__(256, 8)
main_v8(const int* __restrict__ a, const int* __restrict__ b,
        const float* __restrict__ sa, const float* __restrict__ sb,
        const float* __restrict__ so, float* __restrict__ out,
        int n_vec, int vec_per_row, int n, int tail, int D) {
    const int tid = blockIdx.x * blockDim.x + threadIdx.x;
    const int T   = gridDim.x * blockDim.x;   // multiple of vec_per_row
    const int dbase = (tid % vec_per_row) * 8;

    // fused tuple tail: echo scale_out into out[n .. n+tail)
    if (tid < tail) out[n + tid] = (tid < D) ? so[tid] : 0.0f;

    float C[8];
#pragma unroll
    for (int k = 0; k < 8; k++)
        C[k] = __fdiv_rn(sa[dbase + k] * sb[dbase + k], so[dbase + k]);

    // pointer-increment strides: no per-iteration address IMAD.WIDE chains
    const int*   pa = a   + (size_t)tid * 8;
    const int*   pb = b   + (size_t)tid * 8;
    float*       po = out + (size_t)tid * 8;
    const size_t stepi = (size_t)T * 8;

    for (int v = tid; v < n_vec; v += T) {
        unsigned A[8], B[8];
        asm("ld.global.cs.v8.b32 {%0,%1,%2,%3,%4,%5,%6,%7}, [%8];"
            : "=r"(A[0]), "=r"(A[1]), "=r"(A[2]), "=r"(A[3]),
              "=r"(A[4]), "=r"(A[5]), "=r"(A[6]), "=r"(A[7]) : "l"(pa));
        asm("ld.global.cs.v8.b32 {%0,%1,%2,%3,%4,%5,%6,%7}, [%8];"
            : "=r"(B[0]), "=r"(B[1]), "=r"(B[2]), "=r"(B[3]),
              "=r"(B[4]), "=r"(B[5]), "=r"(B[6]), "=r"(B[7]) : "l"(pb));

        unsigned R[8];
#pragma unroll
        for (int k = 0; k < 8; k++) {
            const int p = (int)A[k] * (int)B[k];     // exact, |p| <= 16384
            R[k] = __float_as_uint(requant1((float)p, C[k]));
        }

        asm volatile("st.global.cs.v8.b32 [%0], {%1,%2,%3,%4,%5,%6,%7,%8};"
                     :: "l"(po),
                        "r"(R[0]), "r"(R[1]), "r"(R[2]), "r"(R[3]),
                        "r"(R[4]), "r"(R[5]), "r"(R[6]), "r"(R[7]) : "memory");

        pa += stepi; pb += stepi; po += stepi;
    }
}

// 128-bit fallback (proven R9 shape) for D % 8 != 0.
__global__ void __launch_bounds__(256, 8)
main_v4(const int* __restrict__ a, const int* __restrict__ b,
        const float* __restrict__ sa, const float* __restrict__ sb,
        const float* __restrict__ so, float* __restrict__ out,
        int n_vec, int vec_per_row, int n, int tail, int D) {
    const int tid = blockIdx.x * blockDim.x + threadIdx.x;
    const int T   = gridDim.x * blockDim.x;
    const int dbase = (tid % vec_per_row) * 4;

    if (tid < tail) out[n + tid] = (tid < D) ? so[tid] : 0.0f;

    float C[4];
#pragma unroll
    for (int k = 0; k < 4; k++)
        C[k] = __fdiv_rn(sa[dbase + k] * sb[dbase + k], so[dbase + k]);

    const int4* __restrict__ av = reinterpret_cast<const int4*>(a);
    const int4* __restrict__ bv = reinterpret_cast<const int4*>(b);
    float4* __restrict__ ov = reinterpret_cast<float4*>(out);

#pragma unroll 4
    for (int v = tid; v < n_vec; v += T) {
        const int4 ia = __ldcs(&av[v]);
        const int4 ib = __ldcs(&bv[v]);
        float4 o;
        o.x = requant1((float)(ia.x * ib.x), C[0]);
        o.y = requant1((float)(ia.y * ib.y), C[1]);
        o.z = requant1((float)(ia.z * ib.z), C[2]);
        o.w = requant1((float)(ia.w * ib.w), C[3]);
        __stcs(&ov[v], o);
    }
}

// Generic fallback for shapes where the fast paths' divisibility fails.
__global__ void __launch_bounds__(256)
main_generic(const int* __restrict__ a, const int* __restrict__ b,
             const float* __restrict__ sa, const float* __restrict__ sb,
             const float* __restrict__ so, float* __restrict__ out,
             int n, int D, int tail) {
    const int tid = blockIdx.x * blockDim.x + threadIdx.x;
    const int T   = gridDim.x * blockDim.x;
    if (tid < tail) out[n + tid] = (tid < D) ? so[tid] : 0.0f;
    for (int i = tid; i < n; i += T) {
        const int d = i % D;
        float c = __fdiv_rn(__ldg(&sa[d]) * __ldg(&sb[d]), __ldg(&so[d]));
        out[i] = requant1((float)(a[i] * b[i]), c);
    }
}

extern "C" void kernel_launch(void* const* d_in, const int* in_sizes, int n_in,
                              void* d_out, int out_size) {
    // Identify inputs by element count (ordering-agnostic; a*b and sa*sb
    // commute; scale_out is the last small input in dict AND alpha order).
    long long nmax = 0;
    for (int i = 0; i < n_in; i++)
        if ((long long)in_sizes[i] > nmax) nmax = in_sizes[i];

    const int* big[2] = {nullptr, nullptr};
    const float* scl[3] = {nullptr, nullptr, nullptr};
    int nbig = 0, nscl = 0, D = 0;
    for (int i = 0; i < n_in; i++) {
        if ((long long)in_sizes[i] == nmax && nbig < 2) {
            big[nbig++] = (const int*)d_in[i];
        } else if (nscl < 3) {
            scl[nscl++] = (const float*)d_in[i];
            D = in_sizes[i];
        }
    }
    const int* a = big[0];
    const int* b = big[1] ? big[1] : big[0];
    const float* sa = scl[0];
    const float* sb = scl[1] ? scl[1] : scl[0];
    const float* so = scl[2] ? scl[2] : (scl[1] ? scl[1] : scl[0]);
    float* out = (float*)d_out;

    const int n = (int)nmax;                 // 67,108,864 elements
    if (D <= 0) D = 1024;

    long long tail64 = (long long)out_size - (long long)n;
    if (tail64 < 0) tail64 = 0;

    const int blocks = 1184, threads = 256;  // 8 blocks/SM x 148 SMs, 1 wave
    const long long T = (long long)blocks * threads;   // 303104
    int tail = (int)(tail64 > T ? T : tail64);

    if ((D % 8) == 0 && (n % 8) == 0 && (T % (D / 8)) == 0) {
        main_v8<<<blocks, threads>>>(a, b, sa, sb, so, out,
                                     n / 8, D / 8, n, tail, D);
    } else if ((D % 4) == 0 && (n % 4) == 0 && (T % (D / 4)) == 0) {
        main_v4<<<blocks, threads>>>(a, b, sa, sb, so, out,
                                     n / 4, D / 4, n, tail, D);
    } else {
        main_generic<<<blocks, threads>>>(a, b, sa, sb, so, out, n, D, tail);
    }
}

// round 14
// speedup vs baseline: 1.0270x; 1.0270x over previous
#include <cuda_runtime.h>
#include <cstdint>
#include <math.h>

// ---------------------------------------------------------------------------
// Fused dequant -> multiply -> requant (layout proven by R6-R13 passes):
//   inputs a,b : int32 buffers holding promoted int8 values (67,108,864 elems)
//   scales     : float32[D=1024] each (scale_a, scale_b, scale_out)
//   output     : float32[n + D]; [0,n) = quantized values, [n,n+D) = scale_out
//   out[i] = (float) clip(round_half_even((a*sa)*(b*sb)/so), -128, 127)
//
// R14 = revert to the measured-best R10 kernel form.
// Kernel-time ledger: R10 index-form v8 118.6us (DRAM 81.7%) < cp.async
// 120.1/120.4us < R13 pointer-form v8 126.7us (pointer-carried address
// chains serialized load issue -- reverted). The ~81% DRAM / 6.5TB/s level
// is the 2R:1W turnaround wall, confirmed across 4 kernel structures.
// Frozen: one-wave 1184x256 grid, __launch_bounds__(256,8), 256-bit
// ld/st.global.cs, per-thread register-resident C[8] (fp32 __fdiv_rn),
// fused scale_out tail echo, size-based input identification.
// ---------------------------------------------------------------------------

__device__ __forceinline__ float requant1(float prod, float c) {
    float q = rintf(prod * c);                    // round half to even
    return fminf(fmaxf(q, -128.0f), 127.0f);
}

// vec = 8 elements, one 256-bit load per tensor + one 256-bit store per iter.
// Index-form addressing (a + v*8) -- ptxas issues next iteration's loads off
// the induction variable early; do NOT convert to pointer increments (R13
// measured +8us from the loop-carried pointer chains).
__global__ void __launch_bounds__(256, 8)
main_v8(const int* __restrict__ a, const int* __restrict__ b,
        const float* __restrict__ sa, const float* __restrict__ sb,
        const float* __restrict__ so, float* __restrict__ out,
        int n_vec, int vec_per_row, int n, int tail, int D) {
    const int tid = blockIdx.x * blockDim.x + threadIdx.x;
    const int T   = gridDim.x * blockDim.x;   // multiple of vec_per_row
    const int dbase = (tid % vec_per_row) * 8;

    // fused tuple tail: echo scale_out into out[n .. n+tail)
    if (tid < tail) out[n + tid] = (tid < D) ? so[tid] : 0.0f;

    float C[8];
#pragma unroll
    for (int k = 0; k < 8; k++)
        C[k] = __fdiv_rn(sa[dbase + k] * sb[dbase + k], so[dbase + k]);

    for (int v = tid; v < n_vec; v += T) {
        const int* pa = a + (size_t)v * 8;
        const int* pb = b + (size_t)v * 8;
        float* po = out + (size_t)v * 8;

        unsigned A[8], B[8];
        asm("ld.global.cs.v8.b32 {%0,%1,%2,%3,%4,%5,%6,%7}, [%8];"
            : "=r"(A[0]), "=r"(A[1]), "=r"(A[2]), "=r"(A[3]),
              "=r"(A[4]), "=r"(A[5]), "=r"(A[6]), "=r"(A[7])
            : "l"(pa));
        asm("ld.global.cs.v8.b32 {%0,%1,%2,%3,%4,%5,%6,%7}, [%8];"
            : "=r"(B[0]), "=r"(B[1]), "=r"(B[2]), "=r"(B[3]),
              "=r"(B[4]), "=r"(B[5]), "=r"(B[6]), "=r"(B[7])
            : "l"(pb));

        unsigned R[8];
#pragma unroll
        for (int k = 0; k < 8; k++) {
            const int p = (int)A[k] * (int)B[k];     // exact, |p| <= 16384
            R[k] = __float_as_uint(requant1((float)p, C[k]));
        }

        asm volatile("st.global.cs.v8.b32 [%0], {%1,%2,%3,%4,%5,%6,%7,%8};"
                     :: "l"(po),
                        "r"(R[0]), "r"(R[1]), "r"(R[2]), "r"(R[3]),
                        "r"(R[4]), "r"(R[5]), "r"(R[6]), "r"(R[7])
                     : "memory");
    }
}

// 128-bit fallback (proven R9 shape) for D % 8 != 0.
__global__ void __launch_bounds__(256, 8)
main_v4(const int* __restrict__ a, const int* __restrict__ b,
        const float* __restrict__ sa, const float* __restrict__ sb,
        const float* __restrict__ so, float* __restrict__ out,
        int n_vec, int vec_per_row, int n, int tail, int D) {
    const int tid = blockIdx.x * blockDim.x + threadIdx.x;
    const int T   = gridDim.x * blockDim.x;
    const int dbase = (tid % vec_per_row) * 4;

    if (tid < tail) out[n + tid] = (tid < D) ? so[tid] : 0.0f;

    float C[4];
#pragma unroll
    for (int k = 0; k < 4; k++)
        C[k] = __fdiv_rn(sa[dbase + k] * sb[dbase + k], so[dbase + k]);

    const int4* __restrict__ av = reinterpret_cast<const int4*>(a);
    const int4* __restrict__ bv = reinterpret_cast<const int4*>(b);
    float4* __restrict__ ov = reinterpret_cast<float4*>(out);

#pragma unroll 4
    for (int v = tid; v < n_vec; v += T) {
        const int4 ia = __ldcs(&av[v]);
        const int4 ib = __ldcs(&bv[v]);
        float4 o;
        o.x = requant1((float)(ia.x * ib.x), C[0]);
        o.y = requant1((float)(ia.y * ib.y), C[1]);
        o.z = requant1((float)(ia.z * ib.z), C[2]);
        o.w = requant1((float)(ia.w * ib.w), C[3]);
        __stcs(&ov[v], o);
    }
}

// Generic fallback for shapes where the fast paths' divisibility fails.
__global__ void __launch_bounds__(256)
main_generic(const int* __restrict__ a, const int* __restrict__ b,
             const float* __restrict__ sa, const float* __restrict__ sb,
             const float* __restrict__ so, float* __restrict__ out,
             int n, int D, int tail) {
    const int tid = blockIdx.x * blockDim.x + threadIdx.x;
    const int T   = gridDim.x * blockDim.x;
    if (tid < tail) out[n + tid] = (tid < D) ? so[tid] : 0.0f;
    for (int i = tid; i < n; i += T) {
        const int d = i % D;
        float c = __fdiv_rn(__ldg(&sa[d]) * __ldg(&sb[d]), __ldg(&so[d]));
        out[i] = requant1((float)(a[i] * b[i]), c);
    }
}

extern "C" void kernel_launch(void* const* d_in, const int* in_sizes, int n_in,
                              void* d_out, int out_size) {
    // Identify inputs by element count (ordering-agnostic; a*b and sa*sb
    // commute; scale_out is the last small input in dict AND alpha order).
    long long nmax = 0;
    for (int i = 0; i < n_in; i++)
        if ((long long)in_sizes[i] > nmax) nmax = in_sizes[i];

    const int* big[2] = {nullptr, nullptr};
    const float* scl[3] = {nullptr, nullptr, nullptr};
    int nbig = 0, nscl = 0, D = 0;
    for (int i = 0; i < n_in; i++) {
        if ((long long)in_sizes[i] == nmax && nbig < 2) {
            big[nbig++] = (const int*)d_in[i];
        } else if (nscl < 3) {
            scl[nscl++] = (const float*)d_in[i];
            D = in_sizes[i];
        }
    }
    const int* a = big[0];
    const int* b = big[1] ? big[1] : big[0];
    const float* sa = scl[0];
    const float* sb = scl[1] ? scl[1] : scl[0];
    const float* so = scl[2] ? scl[2] : (scl[1] ? scl[1] : scl[0]);
    float* out = (float*)d_out;

    const int n = (int)nmax;                 // 67,108,864 elements
    if (D <= 0) D = 1024;

    long long tail64 = (long long)out_size - (long long)n;
    if (tail64 < 0) tail64 = 0;

    const int blocks = 1184, threads = 256;  // 8 blocks/SM x 148 SMs, 1 wave
    const long long T = (long long)blocks * threads;   // 303104
    int tail = (int)(tail64 > T ? T : tail64);

    if ((D % 8) == 0 && (n % 8) == 0 && (T % (D / 8)) == 0) {
        main_v8<<<blocks, threads>>>(a, b, sa, sb, so, out,
                                     n / 8, D / 8, n, tail, D);
    } else if ((D % 4) == 0 && (n % 4) == 0 && (T % (D / 4)) == 0) {
        main_v4<<<blocks, threads>>>(a, b, sa, sb, so, out,
                                     n / 4, D / 4, n, tail, D);
    } else {
        main_generic<<<blocks, threads>>>(a, b, sa, sb, so, out, n, D, tail);
    }
}

// round 15
// speedup vs baseline: 1.0285x; 1.0015x over previous
#include <cuda_runtime.h>
#include <cstdint>
#include <math.h>

// ---------------------------------------------------------------------------
// Fused dequant -> multiply -> requant (layout proven by R6-R14 passes):
//   inputs a,b : int32 buffers holding promoted int8 values (67,108,864 elems)
//   scales     : float32[D=1024] each (scale_a, scale_b, scale_out)
//   output     : float32[n + D]; [0,n) = quantized values, [n,n+D) = scale_out
//   out[i] = (float) clip(round_half_even((a*sa)*(b*sb)/so), -128, 127)
//
// FINAL FORM (R15 = R14/R10 measured-best, rebench for variance reduction).
// Kernel-time ledger: v8 index-form 118.6/119.2us (DRAM ~81.5%) beats
// cp.async (120.1/120.4), v4 (131.7), v8 pointer-form (126.7). The ~81%
// DRAM level (~6.45TB/s) is the 2R:1W mixed-stream turnaround ceiling --
// invariant to outstanding-bytes structure, so no structural lever remains.
// dur-kernel gap (7-13us) proven to be harness replay noise (same kernel,
// different draws). Protected invariants:
//   * index-form addressing in the hot loop (pointer-increment form measured
//     +8us: loop-carried 64-bit chains serialize load issue)
//   * one-wave grid 1184x256, __launch_bounds__(256,8), regs<=32
//   * 256-bit ld/st.global.cs (v8.b32), per-thread register C[8] scales
//   * fused scale_out tail echo (out_size = n + D)
//   * size-based input identification (ordering-agnostic)
// ---------------------------------------------------------------------------

__device__ __forceinline__ float requant1(float prod, float c) {
    float q = rintf(prod * c);                    // round half to even
    return fminf(fmaxf(q, -128.0f), 127.0f);
}

// vec = 8 elements, one 256-bit load per tensor + one 256-bit store per iter.
__global__ void __launch_bounds__(256, 8)
main_v8(const int* __restrict__ a, const int* __restrict__ b,
        const float* __restrict__ sa, const float* __restrict__ sb,
        const float* __restrict__ so, float* __restrict__ out,
        int n_vec, int vec_per_row, int n, int tail, int D) {
    const int tid = blockIdx.x * blockDim.x + threadIdx.x;
    const int T   = gridDim.x * blockDim.x;   // multiple of vec_per_row
    const int dbase = (tid % vec_per_row) * 8;

    // fused tuple tail: echo scale_out into out[n .. n+tail)
    if (tid < tail) out[n + tid] = (tid < D) ? so[tid] : 0.0f;

    float C[8];
#pragma unroll
    for (int k = 0; k < 8; k++)
        C[k] = __fdiv_rn(sa[dbase + k] * sb[dbase + k], so[dbase + k]);

    for (int v = tid; v < n_vec; v += T) {
        // index-form addresses (do NOT convert to pointer increments)
        const int* pa = a + (size_t)v * 8;
        const int* pb = b + (size_t)v * 8;
        float* po = out + (size_t)v * 8;

        unsigned A[8], B[8];
        asm("ld.global.cs.v8.b32 {%0,%1,%2,%3,%4,%5,%6,%7}, [%8];"
            : "=r"(A[0]), "=r"(A[1]), "=r"(A[2]), "=r"(A[3]),
              "=r"(A[4]), "=r"(A[5]), "=r"(A[6]), "=r"(A[7])
            : "l"(pa));
        asm("ld.global.cs.v8.b32 {%0,%1,%2,%3,%4,%5,%6,%7}, [%8];"
            : "=r"(B[0]), "=r"(B[1]), "=r"(B[2]), "=r"(B[3]),
              "=r"(B[4]), "=r"(B[5]), "=r"(B[6]), "=r"(B[7])
            : "l"(pb));

        unsigned R[8];
#pragma unroll
        for (int k = 0; k < 8; k++) {
            const int p = (int)A[k] * (int)B[k];     // exact, |p| <= 16384
            R[k] = __float_as_uint(requant1((float)p, C[k]));
        }

        asm volatile("st.global.cs.v8.b32 [%0], {%1,%2,%3,%4,%5,%6,%7,%8};"
                     :: "l"(po),
                        "r"(R[0]), "r"(R[1]), "r"(R[2]), "r"(R[3]),
                        "r"(R[4]), "r"(R[5]), "r"(R[6]), "r"(R[7])
                     : "memory");
    }
}

// 128-bit fallback for D % 8 != 0.
__global__ void __launch_bounds__(256, 8)
main_v4(const int* __restrict__ a, const int* __restrict__ b,
        const float* __restrict__ sa, const float* __restrict__ sb,
        const float* __restrict__ so, float* __restrict__ out,
        int n_vec, int vec_per_row, int n, int tail, int D) {
    const int tid = blockIdx.x * blockDim.x + threadIdx.x;
    const int T   = gridDim.x * blockDim.x;
    const int dbase = (tid % vec_per_row) * 4;

    if (tid < tail) out[n + tid] = (tid < D) ? so[tid] : 0.0f;

    float C[4];
#pragma unroll
    for (int k = 0; k < 4; k++)
        C[k] = __fdiv_rn(sa[dbase + k] * sb[dbase + k], so[dbase + k]);

    const int4* __restrict__ av = reinterpret_cast<const int4*>(a);
    const int4* __restrict__ bv = reinterpret_cast<const int4*>(b);
    float4* __restrict__ ov = reinterpret_cast<float4*>(out);

#pragma unroll 4
    for (int v = tid; v < n_vec; v += T) {
        const int4 ia = __ldcs(&av[v]);
        const int4 ib = __ldcs(&bv[v]);
        float4 o;
        o.x = requant1((float)(ia.x * ib.x), C[0]);
        o.y = requant1((float)(ia.y * ib.y), C[1]);
        o.z = requant1((float)(ia.z * ib.z), C[2]);
        o.w = requant1((float)(ia.w * ib.w), C[3]);
        __stcs(&ov[v], o);
    }
}

// Generic fallback for shapes where the fast paths' divisibility fails.
__global__ void __launch_bounds__(256)
main_generic(const int* __restrict__ a, const int* __restrict__ b,
             const float* __restrict__ sa, const float* __restrict__ sb,
             const float* __restrict__ so, float* __restrict__ out,
             int n, int D, int tail) {
    const int tid = blockIdx.x * blockDim.x + threadIdx.x;
    const int T   = gridDim.x * blockDim.x;
    if (tid < tail) out[n + tid] = (tid < D) ? so[tid] : 0.0f;
    for (int i = tid; i < n; i += T) {
        const int d = i % D;
        float c = __fdiv_rn(__ldg(&sa[d]) * __ldg(&sb[d]), __ldg(&so[d]));
        out[i] = requant1((float)(a[i] * b[i]), c);
    }
}

extern "C" void kernel_launch(void* const* d_in, const int* in_sizes, int n_in,
                              void* d_out, int out_size) {
    // Identify inputs by element count (ordering-agnostic; a*b and sa*sb
    // commute; scale_out is the last small input in dict AND alpha order).
    long long nmax = 0;
    for (int i = 0; i < n_in; i++)
        if ((long long)in_sizes[i] > nmax) nmax = in_sizes[i];

    const int* big[2] = {nullptr, nullptr};
    const float* scl[3] = {nullptr, nullptr, nullptr};
    int nbig = 0, nscl = 0, D = 0;
    for (int i = 0; i < n_in; i++) {
        if ((long long)in_sizes[i] == nmax && nbig < 2) {
            big[nbig++] = (const int*)d_in[i];
        } else if (nscl < 3) {
            scl[nscl++] = (const float*)d_in[i];
            D = in_sizes[i];
        }
    }
    const int* a = big[0];
    const int* b = big[1] ? big[1] : big[0];
    const float* sa = scl[0];
    const float* sb = scl[1] ? scl[1] : scl[0];
    const float* so = scl[2] ? scl[2] : (scl[1] ? scl[1] : scl[0]);
    float* out = (float*)d_out;

    const int n = (int)nmax;                 // 67,108,864 elements
    if (D <= 0) D = 1024;

    long long tail64 = (long long)out_size - (long long)n;
    if (tail64 < 0) tail64 = 0;

    const int blocks = 1184, threads = 256;  // 8 blocks/SM x 148 SMs, 1 wave
    const long long T = (long long)blocks * threads;   // 303104
    int tail = (int)(tail64 > T ? T : tail64);

    if ((D % 8) == 0 && (n % 8) == 0 && (T % (D / 8)) == 0) {
        main_v8<<<blocks, threads>>>(a, b, sa, sb, so, out,
                                     n / 8, D / 8, n, tail, D);
    } else if ((D % 4) == 0 && (n % 4) == 0 && (T % (D / 4)) == 0) {
        main_v4<<<blocks, threads>>>(a, b, sa, sb, so, out,
                                     n / 4, D / 4, n, tail, D);
    } else {
        main_generic<<<blocks, threads>>>(a, b, sa, sb, so, out, n, D, tail);
    }
}

// round 16
// speedup vs baseline: 1.1004x; 1.0700x over previous
#include <cuda_runtime.h>
#include <cstdint>
#include <math.h>

// ---------------------------------------------------------------------------
// Fused dequant -> multiply -> requant (layout proven by R6-R15 passes):
//   inputs a,b : int32 buffers holding promoted int8 values (67,108,864 elems)
//   scales     : float32[D=1024] each (scale_a, scale_b, scale_out)
//   output     : float32[n + D]; [0,n) = quantized values, [n,n+D) = scale_out
//   out[i] = (float) clip(round_half_even((a*sa)*(b*sb)/so), -128, 127)
//
// R16 vs R15 (kernel stable 119.2/119.5us, DRAM ~81%):
//   Last structural hypothesis: one-wave persistent grid (1184 CTAs, ~28
//   iters/thread) pays the slowest-CTA tail (B300 between-SM spread floor
//   ~1.10 from L2 near/far-die variance). Over-decompose to 4736 CTAs
//   (4 waves of 8/SM, ~7 iters/thread) so CLC work scheduling rebalances.
//   Hot loop byte-identical (v8 index-form; pointer form measured +8us).
// ---------------------------------------------------------------------------

__device__ __forceinline__ float requant1(float prod, float c) {
    float q = rintf(prod * c);                    // round half to even
    return fminf(fmaxf(q, -128.0f), 127.0f);
}

// vec = 8 elements, one 256-bit load per tensor + one 256-bit store per iter.
__global__ void __launch_bounds__(256, 8)
main_v8(const int* __restrict__ a, const int* __restrict__ b,
        const float* __restrict__ sa, const float* __restrict__ sb,
        const float* __restrict__ so, float* __restrict__ out,
        int n_vec, int vec_per_row, int n, int tail, int D) {
    const int tid = blockIdx.x * blockDim.x + threadIdx.x;
    const int T   = gridDim.x * blockDim.x;   // multiple of vec_per_row
    const int dbase = (tid % vec_per_row) * 8;

    // fused tuple tail: echo scale_out into out[n .. n+tail)
    if (tid < tail) out[n + tid] = (tid < D) ? so[tid] : 0.0f;

    float C[8];
#pragma unroll
    for (int k = 0; k < 8; k++)
        C[k] = __fdiv_rn(sa[dbase + k] * sb[dbase + k], so[dbase + k]);

    for (int v = tid; v < n_vec; v += T) {
        // index-form addresses (do NOT convert to pointer increments)
        const int* pa = a + (size_t)v * 8;
        const int* pb = b + (size_t)v * 8;
        float* po = out + (size_t)v * 8;

        unsigned A[8], B[8];
        asm("ld.global.cs.v8.b32 {%0,%1,%2,%3,%4,%5,%6,%7}, [%8];"
            : "=r"(A[0]), "=r"(A[1]), "=r"(A[2]), "=r"(A[3]),
              "=r"(A[4]), "=r"(A[5]), "=r"(A[6]), "=r"(A[7])
            : "l"(pa));
        asm("ld.global.cs.v8.b32 {%0,%1,%2,%3,%4,%5,%6,%7}, [%8];"
            : "=r"(B[0]), "=r"(B[1]), "=r"(B[2]), "=r"(B[3]),
              "=r"(B[4]), "=r"(B[5]), "=r"(B[6]), "=r"(B[7])
            : "l"(pb));

        unsigned R[8];
#pragma unroll
        for (int k = 0; k < 8; k++) {
            const int p = (int)A[k] * (int)B[k];     // exact, |p| <= 16384
            R[k] = __float_as_uint(requant1((float)p, C[k]));
        }

        asm volatile("st.global.cs.v8.b32 [%0], {%1,%2,%3,%4,%5,%6,%7,%8};"
                     :: "l"(po),
                        "r"(R[0]), "r"(R[1]), "r"(R[2]), "r"(R[3]),
                        "r"(R[4]), "r"(R[5]), "r"(R[6]), "r"(R[7])
                     : "memory");
    }
}

// 128-bit fallback for D % 8 != 0.
__global__ void __launch_bounds__(256, 8)
main_v4(const int* __restrict__ a, const int* __restrict__ b,
        const float* __restrict__ sa, const float* __restrict__ sb,
        const float* __restrict__ so, float* __restrict__ out,
        int n_vec, int vec_per_row, int n, int tail, int D) {
    const int tid = blockIdx.x * blockDim.x + threadIdx.x;
    const int T   = gridDim.x * blockDim.x;
    const int dbase = (tid % vec_per_row) * 4;

    if (tid < tail) out[n + tid] = (tid < D) ? so[tid] : 0.0f;

    float C[4];
#pragma unroll
    for (int k = 0; k < 4; k++)
        C[k] = __fdiv_rn(sa[dbase + k] * sb[dbase + k], so[dbase + k]);

    const int4* __restrict__ av = reinterpret_cast<const int4*>(a);
    const int4* __restrict__ bv = reinterpret_cast<const int4*>(b);
    float4* __restrict__ ov = reinterpret_cast<float4*>(out);

#pragma unroll 4
    for (int v = tid; v < n_vec; v += T) {
        const int4 ia = __ldcs(&av[v]);
        const int4 ib = __ldcs(&bv[v]);
        float4 o;
        o.x = requant1((float)(ia.x * ib.x), C[0]);
        o.y = requant1((float)(ia.y * ib.y), C[1]);
        o.z = requant1((float)(ia.z * ib.z), C[2]);
        o.w = requant1((float)(ia.w * ib.w), C[3]);
        __stcs(&ov[v], o);
    }
}

// Generic fallback for shapes where the fast paths' divisibility fails.
__global__ void __launch_bounds__(256)
main_generic(const int* __restrict__ a, const int* __restrict__ b,
             const float* __restrict__ sa, const float* __restrict__ sb,
             const float* __restrict__ so, float* __restrict__ out,
             int n, int D, int tail) {
    const int tid = blockIdx.x * blockDim.x + threadIdx.x;
    const int T   = gridDim.x * blockDim.x;
    if (tid < tail) out[n + tid] = (tid < D) ? so[tid] : 0.0f;
    for (int i = tid; i < n; i += T) {
        const int d = i % D;
        float c = __fdiv_rn(__ldg(&sa[d]) * __ldg(&sb[d]), __ldg(&so[d]));
        out[i] = requant1((float)(a[i] * b[i]), c);
    }
}

extern "C" void kernel_launch(void* const* d_in, const int* in_sizes, int n_in,
                              void* d_out, int out_size) {
    // Identify inputs by element count (ordering-agnostic; a*b and sa*sb
    // commute; scale_out is the last small input in dict AND alpha order).
    long long nmax = 0;
    for (int i = 0; i < n_in; i++)
        if ((long long)in_sizes[i] > nmax) nmax = in_sizes[i];

    const int* big[2] = {nullptr, nullptr};
    const float* scl[3] = {nullptr, nullptr, nullptr};
    int nbig = 0, nscl = 0, D = 0;
    for (int i = 0; i < n_in; i++) {
        if ((long long)in_sizes[i] == nmax && nbig < 2) {
            big[nbig++] = (const int*)d_in[i];
        } else if (nscl < 3) {
            scl[nscl++] = (const float*)d_in[i];
            D = in_sizes[i];
        }
    }
    const int* a = big[0];
    const int* b = big[1] ? big[1] : big[0];
    const float* sa = scl[0];
    const float* sb = scl[1] ? scl[1] : scl[0];
    const float* so = scl[2] ? scl[2] : (scl[1] ? scl[1] : scl[0]);
    float* out = (float*)d_out;

    const int n = (int)nmax;                 // 67,108,864 elements
    if (D <= 0) D = 1024;

    long long tail64 = (long long)out_size - (long long)n;
    if (tail64 < 0) tail64 = 0;

    // Over-decomposed grid: 4 waves of 8 CTAs/SM -> CLC rebalances the tail.
    const int blocks = 4736, threads = 256;  // 32 x 148
    const long long T = (long long)blocks * threads;   // 1,212,416
    int tail = (int)(tail64 > T ? T : tail64);

    if ((D % 8) == 0 && (n % 8) == 0 && (T % (D / 8)) == 0) {
        main_v8<<<blocks, threads>>>(a, b, sa, sb, so, out,
                                     n / 8, D / 8, n, tail, D);
    } else if ((D % 4) == 0 && (n % 4) == 0 && (T % (D / 4)) == 0) {
        main_v4<<<blocks, threads>>>(a, b, sa, sb, so, out,
                                     n / 4, D / 4, n, tail, D);
    } else {
        main_generic<<<blocks, threads>>>(a, b, sa, sb, so, out, n, D, tail);
    }
}

// round 17
// speedup vs baseline: 1.1194x; 1.0172x over previous
#include <cuda_runtime.h>
#include <cstdint>
#include <math.h>

// ---------------------------------------------------------------------------
// Fused dequant -> multiply -> requant (layout proven by R6-R16 passes):
//   inputs a,b : int32 buffers holding promoted int8 values (67,108,864 elems)
//   scales     : float32[D=1024] each (scale_a, scale_b, scale_out)
//   output     : float32[n + D]; [0,n) = quantized values, [n,n+D) = scale_out
//   out[i] = (float) clip(round_half_even((a*sa)*(b*sb)/so), -128, 127)
//
// R17 vs R16 (kernel 115.7us, DRAM 83.4%, dur 123.0):
//   Over-decomposition confirmed as a live lever (1184->4736 CTAs bought
//   3.5us by shrinking the slowest-CTA tail quantum). This round:
//   * grid 4736 -> 9472 (8 resident waves, ~3.5 iters/thread) -- halves the
//     tail quantum again;
//   * prologue divide __fdiv_rn -> __fdividef (MUFU.RCP-based, ~4x cheaper)
//     so the doubled per-CTA prologue cost doesn't eat the gain. Division
//     error ~1e-6 rel, far under the 1e-3 gate (expect rel_err <= 5e-5).
//   Hot loop byte-identical (v8 index-form; pointer form measured +8us).
// ---------------------------------------------------------------------------

__device__ __forceinline__ float requant1(float prod, float c) {
    float q = rintf(prod * c);                    // round half to even
    return fminf(fmaxf(q, -128.0f), 127.0f);
}

// vec = 8 elements, one 256-bit load per tensor + one 256-bit store per iter.
__global__ void __launch_bounds__(256, 8)
main_v8(const int* __restrict__ a, const int* __restrict__ b,
        const float* __restrict__ sa, const float* __restrict__ sb,
        const float* __restrict__ so, float* __restrict__ out,
        int n_vec, int vec_per_row, int n, int tail, int D) {
    const int tid = blockIdx.x * blockDim.x + threadIdx.x;
    const int T   = gridDim.x * blockDim.x;   // multiple of vec_per_row
    const int dbase = (tid % vec_per_row) * 8;

    // fused tuple tail: echo scale_out into out[n .. n+tail)
    if (tid < tail) out[n + tid] = (tid < D) ? so[tid] : 0.0f;

    float C[8];
#pragma unroll
    for (int k = 0; k < 8; k++)
        C[k] = __fdividef(sa[dbase + k] * sb[dbase + k], so[dbase + k]);

    for (int v = tid; v < n_vec; v += T) {
        // index-form addresses (do NOT convert to pointer increments)
        const int* pa = a + (size_t)v * 8;
        const int* pb = b + (size_t)v * 8;
        float* po = out + (size_t)v * 8;

        unsigned A[8], B[8];
        asm("ld.global.cs.v8.b32 {%0,%1,%2,%3,%4,%5,%6,%7}, [%8];"
            : "=r"(A[0]), "=r"(A[1]), "=r"(A[2]), "=r"(A[3]),
              "=r"(A[4]), "=r"(A[5]), "=r"(A[6]), "=r"(A[7])
            : "l"(pa));
        asm("ld.global.cs.v8.b32 {%0,%1,%2,%3,%4,%5,%6,%7}, [%8];"
            : "=r"(B[0]), "=r"(B[1]), "=r"(B[2]), "=r"(B[3]),
              "=r"(B[4]), "=r"(B[5]), "=r"(B[6]), "=r"(B[7])
            : "l"(pb));

        unsigned R[8];
#pragma unroll
        for (int k = 0; k < 8; k++) {
            const int p = (int)A[k] * (int)B[k];     // exact, |p| <= 16384
            R[k] = __float_as_uint(requant1((float)p, C[k]));
        }

        asm volatile("st.global.cs.v8.b32 [%0], {%1,%2,%3,%4,%5,%6,%7,%8};"
                     :: "l"(po),
                        "r"(R[0]), "r"(R[1]), "r"(R[2]), "r"(R[3]),
                        "r"(R[4]), "r"(R[5]), "r"(R[6]), "r"(R[7])
                     : "memory");
    }
}

// 128-bit fallback for D % 8 != 0.
__global__ void __launch_bounds__(256, 8)
main_v4(const int* __restrict__ a, const int* __restrict__ b,
        const float* __restrict__ sa, const float* __restrict__ sb,
        const float* __restrict__ so, float* __restrict__ out,
        int n_vec, int vec_per_row, int n, int tail, int D) {
    const int tid = blockIdx.x * blockDim.x + threadIdx.x;
    const int T   = gridDim.x * blockDim.x;
    const int dbase = (tid % vec_per_row) * 4;

    if (tid < tail) out[n + tid] = (tid < D) ? so[tid] : 0.0f;

    float C[4];
#pragma unroll
    for (int k = 0; k < 4; k++)
        C[k] = __fdividef(sa[dbase + k] * sb[dbase + k], so[dbase + k]);

    const int4* __restrict__ av = reinterpret_cast<const int4*>(a);
    const int4* __restrict__ bv = reinterpret_cast<const int4*>(b);
    float4* __restrict__ ov = reinterpret_cast<float4*>(out);

#pragma unroll 4
    for (int v = tid; v < n_vec; v += T) {
        const int4 ia = __ldcs(&av[v]);
        const int4 ib = __ldcs(&bv[v]);
        float4 o;
        o.x = requant1((float)(ia.x * ib.x), C[0]);
        o.y = requant1((float)(ia.y * ib.y), C[1]);
        o.z = requant1((float)(ia.z * ib.z), C[2]);
        o.w = requant1((float)(ia.w * ib.w), C[3]);
        __stcs(&ov[v], o);
    }
}

// Generic fallback for shapes where the fast paths' divisibility fails.
__global__ void __launch_bounds__(256)
main_generic(const int* __restrict__ a, const int* __restrict__ b,
             const float* __restrict__ sa, const float* __restrict__ sb,
             const float* __restrict__ so, float* __restrict__ out,
             int n, int D, int tail) {
    const int tid = blockIdx.x * blockDim.x + threadIdx.x;
    const int T   = gridDim.x * blockDim.x;
    if (tid < tail) out[n + tid] = (tid < D) ? so[tid] : 0.0f;
    for (int i = tid; i < n; i += T) {
        const int d = i % D;
        float c = __fdividef(__ldg(&sa[d]) * __ldg(&sb[d]), __ldg(&so[d]));
        out[i] = requant1((float)(a[i] * b[i]), c);
    }
}

extern "C" void kernel_launch(void* const* d_in, const int* in_sizes, int n_in,
                              void* d_out, int out_size) {
    // Identify inputs by element count (ordering-agnostic; a*b and sa*sb
    // commute; scale_out is the last small input in dict AND alpha order).
    long long nmax = 0;
    for (int i = 0; i < n_in; i++)
        if ((long long)in_sizes[i] > nmax) nmax = in_sizes[i];

    const int* big[2] = {nullptr, nullptr};
    const float* scl[3] = {nullptr, nullptr, nullptr};
    int nbig = 0, nscl = 0, D = 0;
    for (int i = 0; i < n_in; i++) {
        if ((long long)in_sizes[i] == nmax && nbig < 2) {
            big[nbig++] = (const int*)d_in[i];
        } else if (nscl < 3) {
            scl[nscl++] = (const float*)d_in[i];
            D = in_sizes[i];
        }
    }
    const int* a = big[0];
    const int* b = big[1] ? big[1] : big[0];
    const float* sa = scl[0];
    const float* sb = scl[1] ? scl[1] : scl[0];
    const float* so = scl[2] ? scl[2] : (scl[1] ? scl[1] : scl[0]);
    float* out = (float*)d_out;

    const int n = (int)nmax;                 // 67,108,864 elements
    if (D <= 0) D = 1024;

    long long tail64 = (long long)out_size - (long long)n;
    if (tail64 < 0) tail64 = 0;

    // Over-decomposed grid: 8 resident waves of 8 CTAs/SM; CLC rebalances.
    const int blocks = 9472, threads = 256;  // 64 x 148
    const long long T = (long long)blocks * threads;   // 2,424,832
    int tail = (int)(tail64 > T ? T : tail64);

    if ((D % 8) == 0 && (n % 8) == 0 && (T % (D / 8)) == 0) {
        main_v8<<<blocks, threads>>>(a, b, sa, sb, so, out,
                                     n / 8, D / 8, n, tail, D);
    } else if ((D % 4) == 0 && (n % 4) == 0 && (T % (D / 4)) == 0) {
        main_v4<<<blocks, threads>>>(a, b, sa, sb, so, out,
                                     n / 4, D / 4, n, tail, D);
    } else {
        main_generic<<<blocks, threads>>>(a, b, sa, sb, so, out, n, D, tail);
    }
}